// round 2
// baseline (speedup 1.0000x reference)
#include <cuda_runtime.h>
#include <math.h>

#define Bn 128
#define Wn 64
#define En 256
#define Dn 256
#define Fn 4

// Scratch (allocation-free rule: __device__ globals)
__device__ float g_P[Bn * Wn * En];     // P[b,w,e] = enc[b,w,:]·W1_e[e,:] + b1[e]   (8 MB)
__device__ float g_HC[Bn * 2 * Dn];     // [b][0:256]=h, [b][256:512]=c
__device__ float g_S[Bn * En];          // S[b,e] = W1_h·h + W1_c·c
__device__ float g_G[Bn * 4 * Dn];      // Ghh[b,d] = h·w_hh^T + b_ih + b_hh

// ---------------------------------------------------------------------------
__global__ void k_init() {
    int i = blockIdx.x * blockDim.x + threadIdx.x;
    if (i < Bn * 2 * Dn) g_HC[i] = 0.f;
}

// ---------------------------------------------------------------------------
// Precompute P: M=8192 (b*64+w), N=256 (e), K=256.  C = enc · W1_e^T + b1
// 64x64 tile, BK=16, 256 threads, 4x4 micro-tile.
__global__ void k_pre(const float* __restrict__ enc, const float* __restrict__ w1,
                      const float* __restrict__ b1) {
    __shared__ float As[64][17];
    __shared__ float Bs[64][17];
    int tid = threadIdx.x;
    int ty = tid >> 4, tx = tid & 15;
    int m0 = blockIdx.y * 64, n0 = blockIdx.x * 64;
    float acc[4][4] = {};
    for (int k0 = 0; k0 < 256; k0 += 16) {
        int idx = tid * 4;
        int m = idx >> 4, kk = idx & 15;
        float4 va = *reinterpret_cast<const float4*>(&enc[(m0 + m) * 256 + k0 + kk]);
        As[m][kk] = va.x; As[m][kk + 1] = va.y; As[m][kk + 2] = va.z; As[m][kk + 3] = va.w;
        float4 vb = *reinterpret_cast<const float4*>(&w1[(n0 + m) * 768 + 512 + k0 + kk]);
        Bs[m][kk] = vb.x; Bs[m][kk + 1] = vb.y; Bs[m][kk + 2] = vb.z; Bs[m][kk + 3] = vb.w;
        __syncthreads();
#pragma unroll
        for (int k = 0; k < 16; k++) {
            float a[4], b[4];
#pragma unroll
            for (int i = 0; i < 4; i++) a[i] = As[ty * 4 + i][k];
#pragma unroll
            for (int j = 0; j < 4; j++) b[j] = Bs[tx * 4 + j][k];
#pragma unroll
            for (int i = 0; i < 4; i++)
#pragma unroll
                for (int j = 0; j < 4; j++) acc[i][j] += a[i] * b[j];
        }
        __syncthreads();
    }
#pragma unroll
    for (int i = 0; i < 4; i++)
#pragma unroll
        for (int j = 0; j < 4; j++) {
            int n = n0 + tx * 4 + j;
            g_P[(m0 + ty * 4 + i) * 256 + n] = acc[i][j] + b1[n];
        }
}

// ---------------------------------------------------------------------------
// Step kernel A: two GEMMs from g_HC.
//   blocks [0,32):   S   = HC[:,0:512] · w1[:,0:512]^T        M=128 N=256  K=512
//   blocks [32,160): Ghh = HC[:,0:256] · w_hh^T + b_ih+b_hh   M=128 N=1024 K=256
// 32x32 tile, BK=16, 256 threads, 2x2 micro-tile.
__global__ void k_stepA(const float* __restrict__ w1, const float* __restrict__ whh,
                        const float* __restrict__ bih, const float* __restrict__ bhh) {
    __shared__ float As[32][17];
    __shared__ float Bs[32][17];
    int tid = threadIdx.x;
    int ty = tid >> 4, tx = tid & 15;
    int bx = blockIdx.x;
    const float* Bmat; int ldb, K, m0, n0, ldc; float* C; bool isG;
    if (bx < 32) {
        int mt = bx >> 3, nt = bx & 7;
        m0 = mt * 32; n0 = nt * 32;
        Bmat = w1; ldb = 768; K = 512; C = g_S; ldc = 256; isG = false;
    } else {
        int id = bx - 32;
        int mt = id >> 5, nt = id & 31;
        m0 = mt * 32; n0 = nt * 32;
        Bmat = whh; ldb = 256; K = 256; C = g_G; ldc = 1024; isG = true;
    }
    float acc[2][2] = {};
    for (int k0 = 0; k0 < K; k0 += 16) {
        int idx = tid * 2;
        int m = idx >> 4, kk = idx & 15;
        float2 va = *reinterpret_cast<const float2*>(&g_HC[(m0 + m) * 512 + k0 + kk]);
        As[m][kk] = va.x; As[m][kk + 1] = va.y;
        float2 vb = *reinterpret_cast<const float2*>(&Bmat[(n0 + m) * ldb + k0 + kk]);
        Bs[m][kk] = vb.x; Bs[m][kk + 1] = vb.y;
        __syncthreads();
#pragma unroll
        for (int k = 0; k < 16; k++) {
            float a0 = As[ty * 2][k], a1 = As[ty * 2 + 1][k];
            float b0 = Bs[tx * 2][k], b1v = Bs[tx * 2 + 1][k];
            acc[0][0] += a0 * b0; acc[0][1] += a0 * b1v;
            acc[1][0] += a1 * b0; acc[1][1] += a1 * b1v;
        }
        __syncthreads();
    }
#pragma unroll
    for (int i = 0; i < 2; i++)
#pragma unroll
        for (int j = 0; j < 2; j++) {
            int n = n0 + tx * 2 + j;
            float bias = isG ? (bih[n] + bhh[n]) : 0.f;
            C[(m0 + ty * 2 + i) * ldc + n] = acc[i][j] + bias;
        }
}

// ---------------------------------------------------------------------------
// Step kernel B: one block per batch. scores -> softmax -> context -> y_tilde
// -> gates fold (K=4) -> h,c update; at t==63 also the final fcf output.
__global__ void k_stepB(int t, const float* __restrict__ enc,
                        const float* __restrict__ yh,
                        const float* __restrict__ w2, const float* __restrict__ b2,
                        const float* __restrict__ wih,
                        const float* __restrict__ fcw, const float* __restrict__ fcb,
                        const float* __restrict__ fcfw, const float* __restrict__ fcfb,
                        float* __restrict__ out, int last) {
    int b = blockIdx.x;
    int tid = threadIdx.x;
    int lane = tid & 31, wid = tid >> 5;
    __shared__ float sS[256], sScore[64], sAttn[64], sCtx[256], sY[4], sRed[2], sH[256];

    sS[tid] = g_S[b * 256 + tid];
    __syncthreads();

    // scores: 8 warps x 8 windows each; 256-dot per window
    for (int ww = wid; ww < 64; ww += 8) {
        const float* Pp = &g_P[(b * 64 + ww) * 256];
        float part = 0.f;
#pragma unroll
        for (int j = 0; j < 8; j++) {
            int e = lane + 32 * j;
            float z = tanhf(Pp[e] + sS[e]);
            part += w2[e] * z;
        }
#pragma unroll
        for (int o = 16; o; o >>= 1) part += __shfl_xor_sync(0xffffffffu, part, o);
        if (lane == 0) sScore[ww] = part + b2[0];
    }
    __syncthreads();

    // softmax over 64 windows
    if (wid == 0) {
        float v = fmaxf(sScore[lane], sScore[lane + 32]);
#pragma unroll
        for (int o = 16; o; o >>= 1) v = fmaxf(v, __shfl_xor_sync(0xffffffffu, v, o));
        if (lane == 0) sRed[0] = v;
    }
    __syncthreads();
    if (tid < 64) sAttn[tid] = expf(sScore[tid] - sRed[0]);
    __syncthreads();
    if (wid == 0) {
        float v = sAttn[lane] + sAttn[lane + 32];
#pragma unroll
        for (int o = 16; o; o >>= 1) v += __shfl_xor_sync(0xffffffffu, v, o);
        if (lane == 0) sRed[1] = v;
    }
    __syncthreads();
    float inv = 1.f / sRed[1];

    // context[e] = sum_w attn[w]*enc[b,w,e]
    {
        float acc = 0.f;
        const float* ep = &enc[b * 64 * 256 + tid];
#pragma unroll 4
        for (int w = 0; w < 64; w++) acc += sAttn[w] * ep[w * 256];
        sCtx[tid] = acc * inv;
    }
    __syncthreads();

    // y_tilde: 4 warps, K=260
    if (wid < 4) {
        float acc = 0.f;
        const float* fr = &fcw[wid * 260];
        for (int e = lane; e < 256; e += 32) acc += fr[e] * sCtx[e];
#pragma unroll
        for (int o = 16; o; o >>= 1) acc += __shfl_xor_sync(0xffffffffu, acc, o);
        if (lane == 0) {
            float yv = 0.f;
            const float* yp = &yh[(b * 64 + t) * 4];
#pragma unroll
            for (int f = 0; f < 4; f++) yv += fr[256 + f] * yp[f];
            sY[wid] = acc + yv + fcb[wid];
        }
    }
    __syncthreads();

    // gates (fold y_tilde·w_ih^T, K=4) + LSTM update; thread j = hidden unit
    {
        int j = tid;
        float g[4];
#pragma unroll
        for (int q = 0; q < 4; q++) {
            int d = q * 256 + j;
            float4 wr = *reinterpret_cast<const float4*>(&wih[d * 4]);
            g[q] = g_G[b * 1024 + d] + wr.x * sY[0] + wr.y * sY[1] + wr.z * sY[2] + wr.w * sY[3];
        }
        float ig = 1.f / (1.f + expf(-g[0]));
        float fg = 1.f / (1.f + expf(-g[1]));
        float gg = tanhf(g[2]);
        float og = 1.f / (1.f + expf(-g[3]));
        float c_old = g_HC[b * 512 + 256 + j];
        float c_new = fg * c_old + ig * gg;
        float h_new = og * tanhf(c_new);
        g_HC[b * 512 + j] = h_new;
        g_HC[b * 512 + 256 + j] = c_new;
        if (last) sH[j] = h_new;
    }

    // final output: out[b,:] = fcf([h, context]) at the last step
    if (last) {
        __syncthreads();
        if (wid < 4) {
            float acc = 0.f;
            const float* fr = &fcfw[wid * 512];
            for (int i = lane; i < 512; i += 32) {
                float v = (i < 256) ? sH[i] : sCtx[i - 256];
                acc += fr[i] * v;
            }
#pragma unroll
            for (int o = 16; o; o >>= 1) acc += __shfl_xor_sync(0xffffffffu, acc, o);
            if (lane == 0) out[b * 4 + wid] = acc + fcfb[wid];
        }
    }
}

// ---------------------------------------------------------------------------
extern "C" void kernel_launch(void* const* d_in, const int* in_sizes, int n_in,
                              void* d_out, int out_size) {
    const float* enc  = (const float*)d_in[0];
    const float* yh   = (const float*)d_in[1];
    const float* w1   = (const float*)d_in[2];
    const float* b1   = (const float*)d_in[3];
    const float* w2   = (const float*)d_in[4];
    const float* b2   = (const float*)d_in[5];
    const float* wih  = (const float*)d_in[6];
    const float* whh  = (const float*)d_in[7];
    const float* bih  = (const float*)d_in[8];
    const float* bhh  = (const float*)d_in[9];
    const float* fcw  = (const float*)d_in[10];
    const float* fcb  = (const float*)d_in[11];
    const float* fcfw = (const float*)d_in[12];
    const float* fcfb = (const float*)d_in[13];
    float* out = (float*)d_out;

    k_init<<<64, 1024>>>();
    k_pre<<<dim3(4, 128), 256>>>(enc, w1, b1);
    for (int t = 0; t < 64; t++) {
        k_stepA<<<160, 256>>>(w1, whh, bih, bhh);
        k_stepB<<<128, 256>>>(t, enc, yh, w2, b2, wih, fcw, fcb, fcfw, fcfb, out, t == 63);
    }
}

// round 3
// speedup vs baseline: 1.5142x; 1.5142x over previous
#include <cuda_runtime.h>
#include <math.h>

#define Bn 128
#define Wn 64
#define En 256
#define Dn 256

#define NBLK 128
#define NTHR 256

// __device__ scratch (allocation-free rule)
__device__ float g_P[Bn * Wn * En];          // P[b,w,e] (8 MB), staged once
__device__ float g_HC[Bn * 2 * Dn];          // [b][0:256]=h, [b][256:512]=c
__device__ float g_Sh[2 * Bn * En];          // S K-halves (summed in phase B)
__device__ float g_G[Bn * 4 * Dn];           // h·w_hh^T + b_ih + b_hh
__device__ volatile unsigned g_bar_gen;
__device__ unsigned g_bar_cnt;

// ---------------------------------------------------------------------------
__device__ __forceinline__ void grid_barrier() {
    __syncthreads();
    if (threadIdx.x == 0) {
        __threadfence();
        unsigned gen = g_bar_gen;
        if (atomicAdd(&g_bar_cnt, 1u) == NBLK - 1u) {
            atomicExch(&g_bar_cnt, 0u);
            __threadfence();
            g_bar_gen = gen + 1u;
        } else {
            while (g_bar_gen == gen) { __nanosleep(32); }
            __threadfence();
        }
    }
    __syncthreads();
}

// ---------------------------------------------------------------------------
// 32x32 tile GEMM: C[m0:+32, n0:+32] = A[m0:,:K] · B[n0:,:K]^T (+bias1+bias2)
// A row-major lda, B row-major ldb (rows = output cols). 256 threads.
// Transposed smem staging (Ast[k][m]) -> inner loop is 2x float2 LDS per 4 FMA.
// Double-buffered global prefetch. scr needs 2176 floats.
__device__ __forceinline__ void gemm_tile(
    const float* __restrict__ A, int lda,
    const float* __restrict__ B, int ldb,
    float* __restrict__ C, int ldc,
    int m0, int n0, int K,
    const float* __restrict__ bias1, const float* __restrict__ bias2,
    float* scr)
{
    float* Ast = scr;          // [2][16][34]
    float* Bst = scr + 1088;   // [2][16][34]
    const int tid = threadIdx.x;
    const int ty = tid >> 4, tx = tid & 15;
    const int m  = tid >> 3;
    const int kk = (tid & 7) << 1;
    const float* Ap = A + (m0 + m) * lda + kk;
    const float* Bp = B + (n0 + m) * ldb + kk;
    float2 av = *(const float2*)Ap;
    float2 bv = *(const float2*)Bp;
    const int nc = K >> 4;
    float acc00 = 0.f, acc01 = 0.f, acc10 = 0.f, acc11 = 0.f;
    Ast[kk * 34 + m] = av.x;  Ast[(kk + 1) * 34 + m] = av.y;
    Bst[kk * 34 + m] = bv.x;  Bst[(kk + 1) * 34 + m] = bv.y;
    __syncthreads();
    for (int c = 0; c < nc; c++) {
        const int cur = (c & 1) * 544;
        if (c + 1 < nc) {
            av = *(const float2*)(Ap + (c + 1) * 16);
            bv = *(const float2*)(Bp + (c + 1) * 16);
        }
#pragma unroll
        for (int k = 0; k < 16; k++) {
            float2 a = *(const float2*)&Ast[cur + k * 34 + ty * 2];
            float2 b = *(const float2*)&Bst[cur + k * 34 + tx * 2];
            acc00 += a.x * b.x; acc01 += a.x * b.y;
            acc10 += a.y * b.x; acc11 += a.y * b.y;
        }
        if (c + 1 < nc) {
            const int nxt = ((c + 1) & 1) * 544;
            Ast[nxt + kk * 34 + m] = av.x;  Ast[nxt + (kk + 1) * 34 + m] = av.y;
            Bst[nxt + kk * 34 + m] = bv.x;  Bst[nxt + (kk + 1) * 34 + m] = bv.y;
        }
        __syncthreads();
    }
    const int r0 = m0 + ty * 2, c0 = n0 + tx * 2;
    float bb0 = 0.f, bb1 = 0.f;
    if (bias1) { bb0 += bias1[c0]; bb1 += bias1[c0 + 1]; }
    if (bias2) { bb0 += bias2[c0]; bb1 += bias2[c0 + 1]; }
    C[r0 * ldc + c0]           = acc00 + bb0;
    C[r0 * ldc + c0 + 1]       = acc01 + bb1;
    C[(r0 + 1) * ldc + c0]     = acc10 + bb0;
    C[(r0 + 1) * ldc + c0 + 1] = acc11 + bb1;
}

// ---------------------------------------------------------------------------
// Per-step GEMM task table: 192 tasks of 32x32xK256.
//  tasks 0..63   : S K-halves  (kh = t>>5, mt = (t&31)>>3, nt = t&7)
//  tasks 64..191 : Ghh tiles   (g = t-64, mt = g>>5, nt = g&31)
__device__ __forceinline__ void run_task(int t,
    const float* w1, const float* whh, const float* bih, const float* bhh,
    float* scr)
{
    if (t < 64) {
        int kh = t >> 5, r = t & 31;
        int mt = r >> 3, nt = r & 7;
        gemm_tile(g_HC + kh * 256, 512, w1 + kh * 256, 768,
                  g_Sh + kh * (Bn * En), 256,
                  mt * 32, nt * 32, 256, 0, 0, scr);
    } else {
        int g = t - 64;
        int mt = g >> 5, nt = g & 31;
        gemm_tile(g_HC, 512, whh, 256, g_G, 1024,
                  mt * 32, nt * 32, 256, bih, bhh, scr);
    }
}

// ---------------------------------------------------------------------------
__global__ __launch_bounds__(NTHR, 1)
void decoder_persistent(
    const float* __restrict__ enc,  const float* __restrict__ yh,
    const float* __restrict__ w1,   const float* __restrict__ b1,
    const float* __restrict__ w2,   const float* __restrict__ b2,
    const float* __restrict__ wih,  const float* __restrict__ whh,
    const float* __restrict__ bih,  const float* __restrict__ bhh,
    const float* __restrict__ fcw,  const float* __restrict__ fcb,
    const float* __restrict__ fcfw, const float* __restrict__ fcfb,
    float* __restrict__ out)
{
    extern __shared__ float sm[];
    float* sEnc = sm;            // 16384 floats (64 KB)
    float* sP   = sm + 16384;    // 16384 floats (64 KB)
    float* sW2  = sm + 32768;    // 256
    float* scr  = sm + 33024;    // 2176 floats scratch (GEMM tiles / phase-B overlay)
    float* sS    = scr;          // phase-B overlays
    float* sCtx  = scr + 256;
    float* sScore= scr + 512;
    float* sAttn = scr + 576;
    float* sY    = scr + 640;
    float* sRed  = scr + 648;
    float* sH    = scr + 672;

    const int b   = blockIdx.x;
    const int tid = threadIdx.x;
    const int lane = tid & 31, wid = tid >> 5;

    // ---- init: zero h,c for my batch ----
    g_HC[b * 512 + tid]       = 0.f;
    g_HC[b * 512 + 256 + tid] = 0.f;

    // ---- precompute P = enc · W1_e^T + b1 : 2048 tiles, 16 per block ----
    for (int q = 0; q < 16; q++) {
        int tile = b + NBLK * q;          // 0..2047 ; M tiles 256, N tiles 8
        int mt = tile >> 3, nt = tile & 7;
        gemm_tile(enc, 256, w1 + 512, 768, g_P, 256,
                  mt * 32, nt * 32, 256, b1, 0, scr);
    }
    grid_barrier();

    // ---- stage per-batch data in smem (paid once, not per step) ----
    for (int i = tid * 4; i < 16384; i += NTHR * 4) {
        *(float4*)&sEnc[i] = *(const float4*)&enc[b * 16384 + i];
        *(float4*)&sP[i]   = *(const float4*)&g_P[b * 16384 + i];
    }
    sW2[tid] = w2[tid];
    __syncthreads();

    // =======================================================================
    for (int t = 0; t < 64; t++) {
        // ---- phase A: cross-batch GEMMs (S halves + Ghh), <=2 tasks/block --
        run_task(b, w1, whh, bih, bhh, scr);
        if (b < 64) run_task(128 + b, w1, whh, bih, bhh, scr);
        grid_barrier();

        // ---- phase B: per-batch attention + LSTM update (block b) ---------
        sS[tid] = g_Sh[b * 256 + tid] + g_Sh[Bn * En + b * 256 + tid];
        __syncthreads();

        // scores: 8 warps x 8 windows, 256-dot with tanh, all from smem
        for (int ww = wid; ww < 64; ww += 8) {
            const float* Pp = &sP[ww * 256];
            float part = 0.f;
#pragma unroll
            for (int j = 0; j < 8; j++) {
                int e = lane + 32 * j;
                part += sW2[e] * tanhf(Pp[e] + sS[e]);
            }
#pragma unroll
            for (int o = 16; o; o >>= 1) part += __shfl_xor_sync(0xffffffffu, part, o);
            if (lane == 0) sScore[ww] = part + b2[0];
        }
        __syncthreads();

        // softmax over 64 windows
        if (wid == 0) {
            float v = fmaxf(sScore[lane], sScore[lane + 32]);
#pragma unroll
            for (int o = 16; o; o >>= 1) v = fmaxf(v, __shfl_xor_sync(0xffffffffu, v, o));
            if (lane == 0) sRed[0] = v;
        }
        __syncthreads();
        if (tid < 64) sAttn[tid] = expf(sScore[tid] - sRed[0]);
        __syncthreads();
        if (wid == 0) {
            float v = sAttn[lane] + sAttn[lane + 32];
#pragma unroll
            for (int o = 16; o; o >>= 1) v += __shfl_xor_sync(0xffffffffu, v, o);
            if (lane == 0) sRed[1] = v;
        }
        __syncthreads();
        float inv = 1.f / sRed[1];

        // context[e] = sum_w attn[w] * enc[b,w,e]  (all smem)
        {
            float acc = 0.f;
#pragma unroll 8
            for (int w = 0; w < 64; w++) acc += sAttn[w] * sEnc[w * 256 + tid];
            sCtx[tid] = acc * inv;
        }
        __syncthreads();

        // y_tilde = fc([ctx, y_t]) : 4 warps, K=260
        if (wid < 4) {
            float acc = 0.f;
            const float* fr = &fcw[wid * 260];
            for (int e = lane; e < 256; e += 32) acc += fr[e] * sCtx[e];
#pragma unroll
            for (int o = 16; o; o >>= 1) acc += __shfl_xor_sync(0xffffffffu, acc, o);
            if (lane == 0) {
                float yv = 0.f;
                const float* yp = &yh[(b * 64 + t) * 4];
#pragma unroll
                for (int f = 0; f < 4; f++) yv += fr[256 + f] * yp[f];
                sY[wid] = acc + yv + fcb[wid];
            }
        }
        __syncthreads();

        // gates (fold y_tilde · w_ih^T, K=4) + LSTM cell update
        {
            int j = tid;
            float g[4];
#pragma unroll
            for (int q = 0; q < 4; q++) {
                int d = q * 256 + j;
                float4 wr = *(const float4*)&wih[d * 4];
                g[q] = g_G[b * 1024 + d] + wr.x * sY[0] + wr.y * sY[1]
                                         + wr.z * sY[2] + wr.w * sY[3];
            }
            float ig = 1.f / (1.f + expf(-g[0]));
            float fg = 1.f / (1.f + expf(-g[1]));
            float gg = tanhf(g[2]);
            float og = 1.f / (1.f + expf(-g[3]));
            float c_old = g_HC[b * 512 + 256 + j];
            float c_new = fg * c_old + ig * gg;
            float h_new = og * tanhf(c_new);
            g_HC[b * 512 + j]       = h_new;
            g_HC[b * 512 + 256 + j] = c_new;
            if (t == 63) sH[j] = h_new;
        }

        // final output at last step: out[b,:] = fcf([h, ctx])
        if (t == 63) {
            __syncthreads();
            if (wid < 4) {
                float acc = 0.f;
                const float* fr = &fcfw[wid * 512];
                for (int i = lane; i < 512; i += 32) {
                    float v = (i < 256) ? sH[i] : sCtx[i - 256];
                    acc += fr[i] * v;
                }
#pragma unroll
                for (int o = 16; o; o >>= 1) acc += __shfl_xor_sync(0xffffffffu, acc, o);
                if (lane == 0) out[b * 4 + wid] = acc + fcfb[wid];
            }
        }
        grid_barrier();   // h,c visible to next step's phase A
    }
}

// ---------------------------------------------------------------------------
extern "C" void kernel_launch(void* const* d_in, const int* in_sizes, int n_in,
                              void* d_out, int out_size) {
    const float* enc  = (const float*)d_in[0];
    const float* yh   = (const float*)d_in[1];
    const float* w1   = (const float*)d_in[2];
    const float* b1   = (const float*)d_in[3];
    const float* w2   = (const float*)d_in[4];
    const float* b2   = (const float*)d_in[5];
    const float* wih  = (const float*)d_in[6];
    const float* whh  = (const float*)d_in[7];
    const float* bih  = (const float*)d_in[8];
    const float* bhh  = (const float*)d_in[9];
    const float* fcw  = (const float*)d_in[10];
    const float* fcb  = (const float*)d_in[11];
    const float* fcfw = (const float*)d_in[12];
    const float* fcfb = (const float*)d_in[13];
    float* out = (float*)d_out;

    const int smem_bytes = (33024 + 2176) * 4;   // ~137.5 KB
    static int configured = 0;
    if (!configured) {
        cudaFuncSetAttribute(decoder_persistent,
                             cudaFuncAttributeMaxDynamicSharedMemorySize, smem_bytes);
        configured = 1;
    }
    decoder_persistent<<<NBLK, NTHR, smem_bytes>>>(
        enc, yh, w1, b1, w2, b2, wih, whh, bih, bhh, fcw, fcb, fcfw, fcfb, out);
}

// round 4
// speedup vs baseline: 2.0282x; 1.3395x over previous
#include <cuda_runtime.h>
#include <math.h>

#define Bn 128
#define Wn 64
#define En 256
#define Dn 256

#define NBLK 128
#define NTHR 256

// __device__ scratch (allocation-free rule)
__device__ float g_P[Bn * Wn * En];          // P[b,w,e] (8 MB)
__device__ float g_HC[Bn * 2 * Dn];          // [b][0:256]=h, [b][256:512]=c
__device__ float g_Sp[4][Bn * En];           // S K-partials
__device__ float g_Gp[2][Bn * 4 * Dn];       // Ghh K-partials
__device__ volatile unsigned g_bar_gen;
__device__ unsigned g_bar_cnt;

// ---------------------------------------------------------------------------
__device__ __forceinline__ float tanh_fast(float x) {
    float y;
    asm("tanh.approx.f32 %0, %1;" : "=f"(y) : "f"(x));
    return y;
}

__device__ __forceinline__ void grid_barrier() {
    __syncthreads();
    if (threadIdx.x == 0) {
        __threadfence();
        unsigned gen = g_bar_gen;
        if (atomicAdd(&g_bar_cnt, 1u) == NBLK - 1u) {
            atomicExch(&g_bar_cnt, 0u);
            __threadfence();
            g_bar_gen = gen + 1u;
        } else {
            while (g_bar_gen == gen) { __nanosleep(32); }
            __threadfence();
        }
    }
    __syncthreads();
}

// ---------------------------------------------------------------------------
// 64x64 tile GEMM, K = nchunk*128:  C = A(64 x K) · B(64 x K)^T (+bias)
// Aptr = &A[m0][k0] (lda), Bptr = &B[n0][k0] (ldb), Cptr = &C[m0][n0] (ldc).
// 256 threads, 4x4 micro-tile, transposed smem staging (Xst[k][r], stride 64).
// FMA-bound: ~8192 cyc per 128-K chunk.
__device__ __forceinline__ void gemm64(
    const float* __restrict__ Aptr, int lda,
    const float* __restrict__ Bptr, int ldb,
    float* __restrict__ Cptr, int ldc,
    int nchunk, const float* __restrict__ bias,
    float* __restrict__ Ast, float* __restrict__ Bst)
{
    const int tid = threadIdx.x;
    const int r  = tid & 63;          // staging row 0..63
    const int kg = tid >> 6;          // staging k-group 0..3
    const int ty = tid >> 4;          // 0..15 -> rows ty*4..
    const int tx = tid & 15;          // 0..15 -> cols tx*4..
    float acc[4][4] = {};
    for (int c = 0; c < nchunk; c++) {
        const float* Ac = Aptr + c * 128;
        const float* Bc = Bptr + c * 128;
#pragma unroll
        for (int q = 0; q < 8; q++) {
            int k4 = (kg + q * 4) << 2;
            float4 va = *(const float4*)(Ac + r * lda + k4);
            float4 vb = *(const float4*)(Bc + r * ldb + k4);
            Ast[(k4 + 0) * 64 + r] = va.x;
            Ast[(k4 + 1) * 64 + r] = va.y;
            Ast[(k4 + 2) * 64 + r] = va.z;
            Ast[(k4 + 3) * 64 + r] = va.w;
            Bst[(k4 + 0) * 64 + r] = vb.x;
            Bst[(k4 + 1) * 64 + r] = vb.y;
            Bst[(k4 + 2) * 64 + r] = vb.z;
            Bst[(k4 + 3) * 64 + r] = vb.w;
        }
        __syncthreads();
#pragma unroll 8
        for (int k = 0; k < 128; k++) {
            float4 a  = *(const float4*)&Ast[k * 64 + ty * 4];
            float4 bv = *(const float4*)&Bst[k * 64 + tx * 4];
            acc[0][0] += a.x * bv.x; acc[0][1] += a.x * bv.y;
            acc[0][2] += a.x * bv.z; acc[0][3] += a.x * bv.w;
            acc[1][0] += a.y * bv.x; acc[1][1] += a.y * bv.y;
            acc[1][2] += a.y * bv.z; acc[1][3] += a.y * bv.w;
            acc[2][0] += a.z * bv.x; acc[2][1] += a.z * bv.y;
            acc[2][2] += a.z * bv.z; acc[2][3] += a.z * bv.w;
            acc[3][0] += a.w * bv.x; acc[3][1] += a.w * bv.y;
            acc[3][2] += a.w * bv.z; acc[3][3] += a.w * bv.w;
        }
        __syncthreads();
    }
    float4 bb = make_float4(0.f, 0.f, 0.f, 0.f);
    if (bias) bb = *(const float4*)&bias[tx * 4];
#pragma unroll
    for (int i = 0; i < 4; i++) {
        float4 o;
        o.x = acc[i][0] + bb.x;  o.y = acc[i][1] + bb.y;
        o.z = acc[i][2] + bb.z;  o.w = acc[i][3] + bb.w;
        *(float4*)&Cptr[(ty * 4 + i) * ldc + tx * 4] = o;
    }
}

// ---------------------------------------------------------------------------
__global__ __launch_bounds__(NTHR, 1)
void decoder_persistent(
    const float* __restrict__ enc,  const float* __restrict__ yh,
    const float* __restrict__ w1,   const float* __restrict__ b1,
    const float* __restrict__ w2,   const float* __restrict__ b2,
    const float* __restrict__ wih,  const float* __restrict__ whh,
    const float* __restrict__ bih,  const float* __restrict__ bhh,
    const float* __restrict__ fcw,  const float* __restrict__ fcb,
    const float* __restrict__ fcfw, const float* __restrict__ fcfb,
    float* __restrict__ out)
{
    extern __shared__ float sm[];
    float* sEnc = sm;            // 16384 floats
    float* sP   = sm + 16384;    // 16384 floats
    float* sW2  = sm + 32768;    // 256
    float* scr  = sm + 33024;    // 16384 floats: GEMM Ast/Bst | phase-B overlay
    float* Ast  = scr;
    float* Bst  = scr + 8192;
    // phase-B overlay (re-used after phase-A barrier)
    float* sS    = scr;
    float* sCtx  = scr + 256;
    float* sScore= scr + 512;
    float* sAttn = scr + 576;
    float* sY    = scr + 640;
    float* sRed  = scr + 648;
    float* sH    = scr + 672;

    const int b   = blockIdx.x;
    const int tid = threadIdx.x;
    const int lane = tid & 31, wid = tid >> 5;

    // ---- init: zero h,c for my batch ----
    g_HC[b * 512 + tid]       = 0.f;
    g_HC[b * 512 + 256 + tid] = 0.f;

    // ---- precompute P = enc · W1_e^T + b1 : 512 tiles of 64x64xK256 ----
    for (int q = 0; q < 4; q++) {
        int tile = b + NBLK * q;           // 0..511 : mt 0..127, nt 0..3
        int mt = tile >> 2, nt = tile & 3;
        gemm64(enc + mt * 64 * 256, 256,
               w1 + nt * 64 * 768 + 512, 768,
               g_P + mt * 64 * 256 + nt * 64, 256,
               2, b1 + nt * 64, Ast, Bst);
    }
    grid_barrier();

    // ---- stage per-batch data in smem (paid once) ----
    for (int i = tid * 4; i < 16384; i += NTHR * 4) {
        *(float4*)&sEnc[i] = *(const float4*)&enc[b * 16384 + i];
        *(float4*)&sP[i]   = *(const float4*)&g_P[b * 16384 + i];
    }
    sW2[tid] = w2[tid];
    __syncthreads();

    // =======================================================================
    for (int t = 0; t < 64; t++) {
        // ---- phase A: 96 tasks of 64x64x128, one per block ----------------
        if (b < 32) {
            // S partial: kc = b>>3, mt = (b>>2)&1, nt = b&3
            int kc = b >> 3, mt = (b >> 2) & 1, nt = b & 3;
            gemm64(g_HC + mt * 64 * 512 + kc * 128, 512,
                   w1 + nt * 64 * 768 + kc * 128, 768,
                   g_Sp[kc] + mt * 64 * 256 + nt * 64, 256,
                   1, 0, Ast, Bst);
        } else if (b < 96) {
            // Ghh partial: g = b-32; kc = g>>5, mt = (g>>4)&1, nt = g&15
            int g = b - 32;
            int kc = g >> 5, mt = (g >> 4) & 1, nt = g & 15;
            gemm64(g_HC + mt * 64 * 512 + kc * 128, 512,
                   whh + nt * 64 * 256 + kc * 128, 256,
                   g_Gp[kc] + mt * 64 * 1024 + nt * 64, 1024,
                   1, 0, Ast, Bst);
        }
        grid_barrier();

        // ---- phase B: per-batch attention + LSTM update -------------------
        sS[tid] = g_Sp[0][b * 256 + tid] + g_Sp[1][b * 256 + tid]
                + g_Sp[2][b * 256 + tid] + g_Sp[3][b * 256 + tid];
        __syncthreads();

        // scores: 8 warps x 8 windows, 256-dot with HW tanh
        for (int ww = wid; ww < 64; ww += 8) {
            const float* Pp = &sP[ww * 256];
            float part = 0.f;
#pragma unroll
            for (int j = 0; j < 8; j++) {
                int e = lane + 32 * j;
                part += sW2[e] * tanh_fast(Pp[e] + sS[e]);
            }
#pragma unroll
            for (int o = 16; o; o >>= 1) part += __shfl_xor_sync(0xffffffffu, part, o);
            if (lane == 0) sScore[ww] = part + b2[0];
        }
        __syncthreads();

        // softmax over 64 windows
        if (wid == 0) {
            float v = fmaxf(sScore[lane], sScore[lane + 32]);
#pragma unroll
            for (int o = 16; o; o >>= 1) v = fmaxf(v, __shfl_xor_sync(0xffffffffu, v, o));
            if (lane == 0) sRed[0] = v;
        }
        __syncthreads();
        if (tid < 64) sAttn[tid] = __expf(sScore[tid] - sRed[0]);
        __syncthreads();
        if (wid == 0) {
            float v = sAttn[lane] + sAttn[lane + 32];
#pragma unroll
            for (int o = 16; o; o >>= 1) v += __shfl_xor_sync(0xffffffffu, v, o);
            if (lane == 0) sRed[1] = v;
        }
        __syncthreads();
        float inv = 1.f / sRed[1];

        // context[e] = sum_w attn[w] * enc[b,w,e]  (all smem)
        {
            float acc = 0.f;
#pragma unroll 8
            for (int w = 0; w < 64; w++) acc += sAttn[w] * sEnc[w * 256 + tid];
            sCtx[tid] = acc * inv;
        }
        __syncthreads();

        // y_tilde = fc([ctx, y_t]) : 4 warps, K=260
        if (wid < 4) {
            float acc = 0.f;
            const float* fr = &fcw[wid * 260];
            for (int e = lane; e < 256; e += 32) acc += fr[e] * sCtx[e];
#pragma unroll
            for (int o = 16; o; o >>= 1) acc += __shfl_xor_sync(0xffffffffu, acc, o);
            if (lane == 0) {
                float yv = 0.f;
                const float* yp = &yh[(b * 64 + t) * 4];
#pragma unroll
                for (int f = 0; f < 4; f++) yv += fr[256 + f] * yp[f];
                sY[wid] = acc + yv + fcb[wid];
            }
        }
        __syncthreads();

        // gates (sum G partials + fold y_tilde·w_ih^T) + LSTM cell (precise)
        {
            int j = tid;
            float g[4];
#pragma unroll
            for (int q = 0; q < 4; q++) {
                int d = q * 256 + j;
                float4 wr = *(const float4*)&wih[d * 4];
                g[q] = g_Gp[0][b * 1024 + d] + g_Gp[1][b * 1024 + d]
                     + bih[d] + bhh[d]
                     + wr.x * sY[0] + wr.y * sY[1] + wr.z * sY[2] + wr.w * sY[3];
            }
            float ig = 1.f / (1.f + expf(-g[0]));
            float fg = 1.f / (1.f + expf(-g[1]));
            float gg = tanhf(g[2]);
            float og = 1.f / (1.f + expf(-g[3]));
            float c_old = g_HC[b * 512 + 256 + j];
            float c_new = fg * c_old + ig * gg;
            float h_new = og * tanhf(c_new);
            g_HC[b * 512 + j]       = h_new;
            g_HC[b * 512 + 256 + j] = c_new;
            if (t == 63) sH[j] = h_new;
        }

        // final output at last step: out[b,:] = fcf([h, ctx])
        if (t == 63) {
            __syncthreads();
            if (wid < 4) {
                float acc = 0.f;
                const float* fr = &fcfw[wid * 512];
                for (int i = lane; i < 512; i += 32) {
                    float v = (i < 256) ? sH[i] : sCtx[i - 256];
                    acc += fr[i] * v;
                }
#pragma unroll
                for (int o = 16; o; o >>= 1) acc += __shfl_xor_sync(0xffffffffu, acc, o);
                if (lane == 0) out[b * 4 + wid] = acc + fcfb[wid];
            }
        }
        grid_barrier();   // h,c visible to next step's phase A
    }
}

// ---------------------------------------------------------------------------
extern "C" void kernel_launch(void* const* d_in, const int* in_sizes, int n_in,
                              void* d_out, int out_size) {
    const float* enc  = (const float*)d_in[0];
    const float* yh   = (const float*)d_in[1];
    const float* w1   = (const float*)d_in[2];
    const float* b1   = (const float*)d_in[3];
    const float* w2   = (const float*)d_in[4];
    const float* b2   = (const float*)d_in[5];
    const float* wih  = (const float*)d_in[6];
    const float* whh  = (const float*)d_in[7];
    const float* bih  = (const float*)d_in[8];
    const float* bhh  = (const float*)d_in[9];
    const float* fcw  = (const float*)d_in[10];
    const float* fcb  = (const float*)d_in[11];
    const float* fcfw = (const float*)d_in[12];
    const float* fcfb = (const float*)d_in[13];
    float* out = (float*)d_out;

    const int smem_bytes = (16384 + 16384 + 256 + 16384) * 4;   // 193 KB
    static int configured = 0;
    if (!configured) {
        cudaFuncSetAttribute(decoder_persistent,
                             cudaFuncAttributeMaxDynamicSharedMemorySize, smem_bytes);
        configured = 1;
    }
    decoder_persistent<<<NBLK, NTHR, smem_bytes>>>(
        enc, yh, w1, b1, w2, b2, wih, whh, bih, bhh, fcw, fcb, fcfw, fcfb, out);
}

// round 6
// speedup vs baseline: 2.2350x; 1.1019x over previous
#include <cuda_runtime.h>
#include <math.h>

#define Bn 128
#define Wn 64
#define En 256
#define Dn 256

#define NBLK 128
#define NTHR 256

// __device__ scratch (allocation-free rule)
__device__ float g_P[Bn * Wn * En];          // P[b,w,e] (8 MB)
__device__ float g_HC[Bn * 2 * Dn];          // [b][0:256]=h, [b][256:512]=c
__device__ float g_Sp[4][Bn * En];           // S K-partials
__device__ float g_Gp[2][Bn * 4 * Dn];       // Ghh K-partials
__device__ volatile unsigned g_bar_gen;
__device__ unsigned g_bar_cnt;

// ---------------------------------------------------------------------------
__device__ __forceinline__ float tanh_fast(float x) {
    float y;
    asm("tanh.approx.f32 %0, %1;" : "=f"(y) : "f"(x));
    return y;
}
__device__ __forceinline__ unsigned long long pack2(float x, float y) {
    unsigned long long r;
    asm("mov.b64 %0, {%1, %2};" : "=l"(r) : "f"(x), "f"(y));
    return r;
}
__device__ __forceinline__ unsigned long long fma2(unsigned long long a,
                                                   unsigned long long b,
                                                   unsigned long long c) {
    unsigned long long d;
    asm("fma.rn.f32x2 %0, %1, %2, %3;" : "=l"(d) : "l"(a), "l"(b), "l"(c));
    return d;
}
__device__ __forceinline__ float2 unpack2(unsigned long long v) {
    float lo, hi;
    asm("mov.b64 {%0, %1}, %2;" : "=f"(lo), "=f"(hi) : "l"(v));
    return make_float2(lo, hi);
}

__device__ __forceinline__ void grid_barrier() {
    __syncthreads();
    if (threadIdx.x == 0) {
        __threadfence();
        unsigned gen = g_bar_gen;
        if (atomicAdd(&g_bar_cnt, 1u) == NBLK - 1u) {
            atomicExch(&g_bar_cnt, 0u);
            __threadfence();
            g_bar_gen = gen + 1u;
        } else {
            while (g_bar_gen == gen) { __nanosleep(32); }
            __threadfence();
        }
    }
    __syncthreads();
}

// ---------------------------------------------------------------------------
// Stage 64 rows x 128 k of X (row-major ldx) into Xst[k][r] (stride 64).
__device__ __forceinline__ void stage64x128(const float* __restrict__ Xp, int ldx,
                                            float* __restrict__ Xst) {
    const int tid = threadIdx.x;
    const int r  = tid & 63;
    const int kg = tid >> 6;
#pragma unroll
    for (int q = 0; q < 8; q++) {
        int k4 = (kg + q * 4) << 2;
        float4 v = *(const float4*)(Xp + r * ldx + k4);
        Xst[(k4 + 0) * 64 + r] = v.x;
        Xst[(k4 + 1) * 64 + r] = v.y;
        Xst[(k4 + 2) * 64 + r] = v.z;
        Xst[(k4 + 3) * 64 + r] = v.w;
    }
}

// 64x64 x 128k accumulate with packed f32x2 FMA. acc[4][2] packed pairs.
__device__ __forceinline__ void mma128(const float* __restrict__ Ast,
                                       const float* __restrict__ Bst,
                                       unsigned long long acc[4][2]) {
    const int ty = threadIdx.x >> 4, tx = threadIdx.x & 15;
#pragma unroll 8
    for (int k = 0; k < 128; k++) {
        float4 a = *(const float4*)&Ast[k * 64 + ty * 4];
        ulonglong2 b = *(const ulonglong2*)&Bst[k * 64 + tx * 4];
        unsigned long long a0 = pack2(a.x, a.x);
        unsigned long long a1 = pack2(a.y, a.y);
        unsigned long long a2 = pack2(a.z, a.z);
        unsigned long long a3 = pack2(a.w, a.w);
        acc[0][0] = fma2(a0, b.x, acc[0][0]); acc[0][1] = fma2(a0, b.y, acc[0][1]);
        acc[1][0] = fma2(a1, b.x, acc[1][0]); acc[1][1] = fma2(a1, b.y, acc[1][1]);
        acc[2][0] = fma2(a2, b.x, acc[2][0]); acc[2][1] = fma2(a2, b.y, acc[2][1]);
        acc[3][0] = fma2(a3, b.x, acc[3][0]); acc[3][1] = fma2(a3, b.y, acc[3][1]);
    }
}

__device__ __forceinline__ void epilogue(unsigned long long acc[4][2],
                                         float* __restrict__ Cptr, int ldc,
                                         const float* __restrict__ bias) {
    const int ty = threadIdx.x >> 4, tx = threadIdx.x & 15;
    float4 bb = make_float4(0.f, 0.f, 0.f, 0.f);
    if (bias) bb = *(const float4*)&bias[tx * 4];
#pragma unroll
    for (int i = 0; i < 4; i++) {
        float2 lo = unpack2(acc[i][0]);
        float2 hi = unpack2(acc[i][1]);
        float4 o;
        o.x = lo.x + bb.x; o.y = lo.y + bb.y;
        o.z = hi.x + bb.z; o.w = hi.y + bb.w;
        *(float4*)&Cptr[(ty * 4 + i) * ldc + tx * 4] = o;
    }
}

// Full tile GEMM (stages both operands) for the precompute.
__device__ __forceinline__ void gemm64_full(
    const float* __restrict__ Aptr, int lda,
    const float* __restrict__ Bptr, int ldb,
    float* __restrict__ Cptr, int ldc,
    int nchunk, const float* __restrict__ bias,
    float* __restrict__ Ast, float* __restrict__ Bst)
{
    unsigned long long acc[4][2];
#pragma unroll
    for (int i = 0; i < 4; i++) { acc[i][0] = 0ull; acc[i][1] = 0ull; }
    for (int c = 0; c < nchunk; c++) {
        stage64x128(Aptr + c * 128, lda, Ast);
        stage64x128(Bptr + c * 128, ldb, Bst);
        __syncthreads();
        mma128(Ast, Bst, acc);
        __syncthreads();
    }
    epilogue(acc, Cptr, ldc, bias);
}

// ---------------------------------------------------------------------------
__global__ __launch_bounds__(NTHR, 1)
void decoder_persistent(
    const float* __restrict__ enc,  const float* __restrict__ yh,
    const float* __restrict__ w1,   const float* __restrict__ b1,
    const float* __restrict__ w2,   const float* __restrict__ b2,
    const float* __restrict__ wih,  const float* __restrict__ whh,
    const float* __restrict__ bih,  const float* __restrict__ bhh,
    const float* __restrict__ fcw,  const float* __restrict__ fcb,
    const float* __restrict__ fcfw, const float* __restrict__ fcfb,
    float* __restrict__ out)
{
    extern __shared__ float sm[];
    float* sEnc = sm;            // 16384
    float* sP   = sm + 16384;    // 16384
    float* sW2  = sm + 32768;    // 256
    float* scr  = sm + 33024;    // 16384: [Ast 8192 | Bw 8192]
    float* Ast  = scr;
    float* Bw   = scr + 8192;    // persistent per-block weight tile (after init)
    // phase-B overlay (Ast region only; Bw stays live)
    float* sS    = scr;
    float* sCtx  = scr + 256;
    float* sScore= scr + 512;
    float* sAttn = scr + 576;
    float* sY    = scr + 640;
    float* sRed  = scr + 648;
    float* sH    = scr + 672;

    const int b   = blockIdx.x;
    const int tid = threadIdx.x;
    const int lane = tid & 31, wid = tid >> 5;

    // ---- init: zero h,c for my batch ----
    g_HC[b * 512 + tid]       = 0.f;
    g_HC[b * 512 + 256 + tid] = 0.f;

    // ---- precompute P = enc · W1_e^T + b1 : 512 tiles of 64x64x256 ----
    for (int q = 0; q < 4; q++) {
        int tile = b + NBLK * q;           // mt 0..127, nt 0..3
        int mt = tile >> 2, nt = tile & 3;
        gemm64_full(enc + mt * 64 * 256, 256,
                    w1 + nt * 64 * 768 + 512, 768,
                    g_P + mt * 64 * 256 + nt * 64, 256,
                    2, b1 + nt * 64, Ast, Bw);
    }
    grid_barrier();

    // ---- decode my fixed per-step GEMM task ----
    const float* taskA = 0;  const float* taskW = 0;
    float* taskC = 0; int taskLdw = 0, taskLdc = 0;
    if (b < 32) {
        int kc = b >> 3, mt = (b >> 2) & 1, nt = b & 3;
        taskA = g_HC + mt * 64 * 512 + kc * 128;
        taskW = w1 + nt * 64 * 768 + kc * 128;  taskLdw = 768;
        taskC = g_Sp[kc] + mt * 64 * 256 + nt * 64;  taskLdc = 256;
    } else if (b < 96) {
        int g = b - 32;
        int kc = g >> 5, mt = (g >> 4) & 1, nt = g & 15;
        taskA = g_HC + mt * 64 * 512 + kc * 128;
        taskW = whh + nt * 64 * 256 + kc * 128;  taskLdw = 256;
        taskC = g_Gp[kc] + mt * 64 * 1024 + nt * 64;  taskLdc = 1024;
    }

    // ---- stage per-batch data + persistent weight tile in smem (once) ----
    for (int i = tid * 4; i < 16384; i += NTHR * 4) {
        *(float4*)&sEnc[i] = *(const float4*)&enc[b * 16384 + i];
        *(float4*)&sP[i]   = *(const float4*)&g_P[b * 16384 + i];
    }
    sW2[tid] = w2[tid];
    if (taskW) stage64x128(taskW, taskLdw, Bw);
    __syncthreads();

    // =======================================================================
    for (int t = 0; t < 64; t++) {
        // ---- phase A: one 64x64x128 task per block (B operand resident) ---
        if (taskA) {
            stage64x128(taskA, 512, Ast);
            __syncthreads();
            unsigned long long acc[4][2];
#pragma unroll
            for (int i = 0; i < 4; i++) { acc[i][0] = 0ull; acc[i][1] = 0ull; }
            mma128(Ast, Bw, acc);
            epilogue(acc, taskC, taskLdc, 0);
        }
        grid_barrier();

        // ---- phase B: per-batch attention + LSTM update -------------------
        {
            float2 p0 = *(const float2*)&g_Sp[0][b * 256 + (tid & ~1)];
            float2 p1 = *(const float2*)&g_Sp[1][b * 256 + (tid & ~1)];
            float2 p2 = *(const float2*)&g_Sp[2][b * 256 + (tid & ~1)];
            float2 p3 = *(const float2*)&g_Sp[3][b * 256 + (tid & ~1)];
            sS[tid] = (tid & 1) ? (p0.y + p1.y + p2.y + p3.y)
                                : (p0.x + p1.x + p2.x + p3.x);
        }
        __syncthreads();

        // scores: 8 warps x 8 windows, 256-dot with HW tanh
        for (int ww = wid; ww < 64; ww += 8) {
            const float* Pp = &sP[ww * 256];
            float part = 0.f;
#pragma unroll
            for (int j = 0; j < 8; j++) {
                int e = lane + 32 * j;
                part += sW2[e] * tanh_fast(Pp[e] + sS[e]);
            }
#pragma unroll
            for (int o = 16; o; o >>= 1) part += __shfl_xor_sync(0xffffffffu, part, o);
            if (lane == 0) sScore[ww] = part + b2[0];
        }
        __syncthreads();

        // softmax over 64 windows
        if (wid == 0) {
            float v = fmaxf(sScore[lane], sScore[lane + 32]);
#pragma unroll
            for (int o = 16; o; o >>= 1) v = fmaxf(v, __shfl_xor_sync(0xffffffffu, v, o));
            if (lane == 0) sRed[0] = v;
        }
        __syncthreads();
        if (tid < 64) sAttn[tid] = __expf(sScore[tid] - sRed[0]);
        __syncthreads();
        if (wid == 0) {
            float v = sAttn[lane] + sAttn[lane + 32];
#pragma unroll
            for (int o = 16; o; o >>= 1) v += __shfl_xor_sync(0xffffffffu, v, o);
            if (lane == 0) sRed[1] = v;
        }
        __syncthreads();
        float inv = 1.f / sRed[1];

        // context[e] = sum_w attn[w] * enc[b,w,e]  (all smem)
        {
            float acc = 0.f;
#pragma unroll 8
            for (int w = 0; w < 64; w++) acc += sAttn[w] * sEnc[w * 256 + tid];
            sCtx[tid] = acc * inv;
        }
        __syncthreads();

        // y_tilde = fc([ctx, y_t]) : 4 warps, K=260
        if (wid < 4) {
            float acc = 0.f;
            const float* fr = &fcw[wid * 260];
            for (int e = lane; e < 256; e += 32) acc += fr[e] * sCtx[e];
#pragma unroll
            for (int o = 16; o; o >>= 1) acc += __shfl_xor_sync(0xffffffffu, acc, o);
            if (lane == 0) {
                float yv = 0.f;
                const float* yp = &yh[(b * 64 + t) * 4];
#pragma unroll
                for (int f = 0; f < 4; f++) yv += fr[256 + f] * yp[f];
                sY[wid] = acc + yv + fcb[wid];
            }
        }
        __syncthreads();

        // gates (sum G partials + fold y_tilde·w_ih^T) + LSTM cell (precise)
        {
            int j = tid;
            float g[4];
#pragma unroll
            for (int q = 0; q < 4; q++) {
                int d = q * 256 + j;
                float4 wr = *(const float4*)&wih[d * 4];
                g[q] = g_Gp[0][b * 1024 + d] + g_Gp[1][b * 1024 + d]
                     + bih[d] + bhh[d]
                     + wr.x * sY[0] + wr.y * sY[1] + wr.z * sY[2] + wr.w * sY[3];
            }
            float ig = 1.f / (1.f + expf(-g[0]));
            float fg = 1.f / (1.f + expf(-g[1]));
            float gg = tanhf(g[2]);
            float og = 1.f / (1.f + expf(-g[3]));
            float c_old = g_HC[b * 512 + 256 + j];
            float c_new = fg * c_old + ig * gg;
            float h_new = og * tanhf(c_new);
            g_HC[b * 512 + j]       = h_new;
            g_HC[b * 512 + 256 + j] = c_new;
            if (t == 63) sH[j] = h_new;
        }

        // final output at last step: out[b,:] = fcf([h, ctx])
        if (t == 63) {
            __syncthreads();
            if (wid < 4) {
                float acc = 0.f;
                const float* fr = &fcfw[wid * 512];
                for (int i = lane; i < 512; i += 32) {
                    float v = (i < 256) ? sH[i] : sCtx[i - 256];
                    acc += fr[i] * v;
                }
#pragma unroll
                for (int o = 16; o; o >>= 1) acc += __shfl_xor_sync(0xffffffffu, acc, o);
                if (lane == 0) out[b * 4 + wid] = acc + fcfb[wid];
            }
        }
        grid_barrier();   // h,c visible to next step's phase A
    }
}

// ---------------------------------------------------------------------------
extern "C" void kernel_launch(void* const* d_in, const int* in_sizes, int n_in,
                              void* d_out, int out_size) {
    const float* enc  = (const float*)d_in[0];
    const float* yh   = (const float*)d_in[1];
    const float* w1   = (const float*)d_in[2];
    const float* b1   = (const float*)d_in[3];
    const float* w2   = (const float*)d_in[4];
    const float* b2   = (const float*)d_in[5];
    const float* wih  = (const float*)d_in[6];
    const float* whh  = (const float*)d_in[7];
    const float* bih  = (const float*)d_in[8];
    const float* bhh  = (const float*)d_in[9];
    const float* fcw  = (const float*)d_in[10];
    const float* fcb  = (const float*)d_in[11];
    const float* fcfw = (const float*)d_in[12];
    const float* fcfb = (const float*)d_in[13];
    float* out = (float*)d_out;

    const int smem_bytes = (16384 + 16384 + 256 + 16384) * 4;   // 193 KB
    static int configured = 0;
    if (!configured) {
        cudaFuncSetAttribute(decoder_persistent,
                             cudaFuncAttributeMaxDynamicSharedMemorySize, smem_bytes);
        configured = 1;
    }
    decoder_persistent<<<NBLK, NTHR, smem_bytes>>>(
        enc, yh, w1, b1, w2, b2, wih, whh, bih, bhh, fcw, fcb, fcfw, fcfb, out);
}